// round 1
// baseline (speedup 1.0000x reference)
#include <cuda_runtime.h>
#include <math.h>

// Problem constants (fixed by the reference):
//   N=4096 nodes, H=256, HEADS=4, DH=64, E=262144 edges, fp32 everywhere,
//   edge_index int32, output (N,H) fp32.
#define Nn 4096
#define Hh 256
#define NHEADS 4
#define DHd 64
#define Ee 262144

// ---------------- scratch (static device globals; no runtime allocation) ----
__device__ int   g_degi[Nn];
__device__ int   g_rowptr[Nn + 1];
__device__ int   g_cursor[Nn];
__device__ int   g_col[Ee];
__device__ float g_rw[Nn];
__device__ float g_bsum[Hh];
__device__ float g_X1[Nn * Hh];
__device__ float g_X2[Nn * Hh];
__device__ float g_agg[Nn * Hh];
__device__ float g_q[Nn * Hh];
__device__ float g_k[Nn * Hh];
__device__ float g_v[Nn * Hh];
__device__ float g_ctx[Nn * Hh];
__device__ float g_o[Nn * Hh];
__device__ float g_x[Nn * Hh];
__device__ float g_t[Nn * 2 * Hh];
__device__ float g_y[Nn * Hh];

// ---------------- graph preprocessing ---------------------------------------
__global__ void zero_kernel() {
    int i = blockIdx.x * blockDim.x + threadIdx.x;
    if (i < Nn) g_degi[i] = 0;
}

__global__ void deg_kernel(const int* __restrict__ ei) {
    int e = blockIdx.x * blockDim.x + threadIdx.x;
    if (e < Ee) atomicAdd(&g_degi[ei[Ee + e]], 1);
}

// single-block Hillis-Steele scan over 4096 degrees (4 per thread)
__global__ void prefix_kernel() {
    __shared__ int sm[1024];
    int t = threadIdx.x;
    int b = t * 4;
    int d0 = g_degi[b], d1 = g_degi[b + 1], d2 = g_degi[b + 2], d3 = g_degi[b + 3];
    int tot = d0 + d1 + d2 + d3;
    sm[t] = tot;
    __syncthreads();
    for (int off = 1; off < 1024; off <<= 1) {
        int v = 0;
        if (t >= off) v = sm[t - off];
        __syncthreads();
        if (t >= off) sm[t] += v;
        __syncthreads();
    }
    int excl = sm[t] - tot;
    g_rowptr[b]     = excl; g_cursor[b]     = excl; excl += d0;
    g_rowptr[b + 1] = excl; g_cursor[b + 1] = excl; excl += d1;
    g_rowptr[b + 2] = excl; g_cursor[b + 2] = excl; excl += d2;
    g_rowptr[b + 3] = excl; g_cursor[b + 3] = excl; excl += d3;
    if (t == 1023) g_rowptr[Nn] = excl;
}

__global__ void fill_kernel(const int* __restrict__ ei) {
    int e = blockIdx.x * blockDim.x + threadIdx.x;
    if (e < Ee) {
        int dst = ei[Ee + e];
        int pos = atomicAdd(&g_cursor[dst], 1);
        g_col[pos] = ei[e];
    }
}

// Per node n: X1[n] = (sum of h[src] over in-edges)/max(d,1);
//            X2[n] = h[n]*[d>0]; rw[n] = [d>0].
__global__ void aggsum_kernel(const float* __restrict__ h) {
    int n = blockIdx.x;
    int c = threadIdx.x;
    int s0 = g_rowptr[n], s1 = g_rowptr[n + 1];
    int d = s1 - s0;
    float inv = 1.0f / (float)max(d, 1);
    float rwv = d > 0 ? 1.0f : 0.0f;
    float sum = 0.0f;
    int e = s0;
    for (; e + 4 <= s1; e += 4) {
        int c0 = g_col[e], c1 = g_col[e + 1], c2 = g_col[e + 2], c3 = g_col[e + 3];
        sum += h[(size_t)c0 * Hh + c];
        sum += h[(size_t)c1 * Hh + c];
        sum += h[(size_t)c2 * Hh + c];
        sum += h[(size_t)c3 * Hh + c];
    }
    for (; e < s1; e++) sum += h[(size_t)g_col[e] * Hh + c];
    g_X1[(size_t)n * Hh + c] = sum * inv;
    g_X2[(size_t)n * Hh + c] = h[(size_t)n * Hh + c] * rwv;
    if (c == 0) g_rw[n] = rwv;
}

__global__ void bsum_kernel(const float* __restrict__ a, const float* __restrict__ b) {
    int c = threadIdx.x;
    g_bsum[c] = a[c] + b[c];
}

// ---------------- generic fp32 tiled GEMM -----------------------------------
// C[M,Nc] = A[M,K] @ B[K,Nc] (+ bias[n] * (rowScale?rowScale[m]:1)) (+= C if accumulate)
// ACT: 0 = none, 1 = exact gelu
template <int ACT>
__global__ void __launch_bounds__(256) gemm_kernel(
    const float* __restrict__ A, const float* __restrict__ B,
    const float* __restrict__ bias, const float* __restrict__ rowScale,
    float* __restrict__ C, int M, int K, int Nc, int accumulate)
{
    __shared__ float As[16][68];  // A^T tile, padded (16B-aligned rows)
    __shared__ float Bs[16][64];
    int tid = threadIdx.x;
    int ty = tid >> 4, tx = tid & 15;
    int m0 = blockIdx.y * 64, n0 = blockIdx.x * 64;
    int arow = tid >> 2, ak = (tid & 3) * 4;
    int brow = tid >> 4, bc = (tid & 15) * 4;
    float acc[4][4] = {};
    for (int k0 = 0; k0 < K; k0 += 16) {
        float4 a = *(const float4*)(A + (size_t)(m0 + arow) * K + k0 + ak);
        As[ak + 0][arow] = a.x;
        As[ak + 1][arow] = a.y;
        As[ak + 2][arow] = a.z;
        As[ak + 3][arow] = a.w;
        float4 b = *(const float4*)(B + (size_t)(k0 + brow) * Nc + n0 + bc);
        *(float4*)&Bs[brow][bc] = b;
        __syncthreads();
#pragma unroll
        for (int kk = 0; kk < 16; kk++) {
            float4 ra4 = *(const float4*)&As[kk][ty * 4];
            float4 rb4 = *(const float4*)&Bs[kk][tx * 4];
            float ra[4] = {ra4.x, ra4.y, ra4.z, ra4.w};
            float rb[4] = {rb4.x, rb4.y, rb4.z, rb4.w};
#pragma unroll
            for (int i = 0; i < 4; i++)
#pragma unroll
                for (int j = 0; j < 4; j++)
                    acc[i][j] = fmaf(ra[i], rb[j], acc[i][j]);
        }
        __syncthreads();
    }
#pragma unroll
    for (int i = 0; i < 4; i++) {
        int m = m0 + ty * 4 + i;
#pragma unroll
        for (int j = 0; j < 4; j++) {
            int n = n0 + tx * 4 + j;
            float vv = acc[i][j];
            if (bias) {
                float bv = bias[n];
                if (rowScale) bv *= rowScale[m];
                vv += bv;
            }
            if (accumulate) vv += C[(size_t)m * Nc + n];
            if (ACT == 1) vv = 0.5f * vv * (1.0f + erff(vv * 0.7071067811865476f));
            C[(size_t)m * Nc + n] = vv;
        }
    }
}

// ---------------- flash attention (fp32 SIMT) --------------------------------
// One block = (64 queries) x (1 head). Online softmax over all 4096 keys,
// 64-key tiles. Softmax in exp2 domain; 1/8*log2(e) folded into Q at load.
__global__ void __launch_bounds__(256) attn_kernel(
    const float* __restrict__ q, const float* __restrict__ k,
    const float* __restrict__ v, float* __restrict__ ctx)
{
    extern __shared__ float smem[];
    float* Qs = smem;                  // [64][68]  Qs[d][r]   (transposed)
    float* Ks = smem + 64 * 68;        // [64][68]  Ks[d][j]   (transposed)
    float* Ps = smem + 2 * 64 * 68;    // [64][68]  Ps[r][kk]  (natural)
    float* Vs = smem + 3 * 64 * 68;    // [64][64]  Vs[kk][d]  (natural)

    int tid = threadIdx.x;
    int ty = tid >> 4, tx = tid & 15;
    int hd = blockIdx.y;
    int q0 = blockIdx.x * 64;
    const float qscale = 0.125f * 1.4426950408889634f;

#pragma unroll
    for (int it = 0; it < 4; it++) {
        int idx = tid + it * 256;
        int r = idx >> 4, d4 = (idx & 15) * 4;
        float4 a = *(const float4*)(q + (size_t)(q0 + r) * Hh + hd * DHd + d4);
        Qs[(d4 + 0) * 68 + r] = a.x * qscale;
        Qs[(d4 + 1) * 68 + r] = a.y * qscale;
        Qs[(d4 + 2) * 68 + r] = a.z * qscale;
        Qs[(d4 + 3) * 68 + r] = a.w * qscale;
    }

    float O[4][4] = {};
    float mr[4] = {-1e30f, -1e30f, -1e30f, -1e30f};
    float lr[4] = {};

    for (int kb = 0; kb < Nn; kb += 64) {
#pragma unroll
        for (int it = 0; it < 4; it++) {
            int idx = tid + it * 256;
            int r = idx >> 4, d4 = (idx & 15) * 4;
            float4 a = *(const float4*)(k + (size_t)(kb + r) * Hh + hd * DHd + d4);
            Ks[(d4 + 0) * 68 + r] = a.x;
            Ks[(d4 + 1) * 68 + r] = a.y;
            Ks[(d4 + 2) * 68 + r] = a.z;
            Ks[(d4 + 3) * 68 + r] = a.w;
            float4 b = *(const float4*)(v + (size_t)(kb + r) * Hh + hd * DHd + d4);
            *(float4*)&Vs[r * 64 + d4] = b;
        }
        __syncthreads();

        float s[4][4] = {};
#pragma unroll 8
        for (int kk = 0; kk < 64; kk++) {
            float4 qa = *(const float4*)&Qs[kk * 68 + ty * 4];
            float4 kb4 = *(const float4*)&Ks[kk * 68 + tx * 4];
            float ra[4] = {qa.x, qa.y, qa.z, qa.w};
            float rb[4] = {kb4.x, kb4.y, kb4.z, kb4.w};
#pragma unroll
            for (int i = 0; i < 4; i++)
#pragma unroll
                for (int j = 0; j < 4; j++)
                    s[i][j] = fmaf(ra[i], rb[j], s[i][j]);
        }

        // online softmax (row stats reduced across the 16 lanes sharing ty)
#pragma unroll
        for (int i = 0; i < 4; i++) {
            float rm = fmaxf(fmaxf(s[i][0], s[i][1]), fmaxf(s[i][2], s[i][3]));
#pragma unroll
            for (int off = 1; off < 16; off <<= 1)
                rm = fmaxf(rm, __shfl_xor_sync(0xffffffffu, rm, off));
            float mn = fmaxf(mr[i], rm);
            float cc = exp2f(mr[i] - mn);
            mr[i] = mn;
            float p0 = exp2f(s[i][0] - mn);
            float p1 = exp2f(s[i][1] - mn);
            float p2 = exp2f(s[i][2] - mn);
            float p3 = exp2f(s[i][3] - mn);
            float ps = p0 + p1 + p2 + p3;
#pragma unroll
            for (int off = 1; off < 16; off <<= 1)
                ps += __shfl_xor_sync(0xffffffffu, ps, off);
            lr[i] = lr[i] * cc + ps;
            O[i][0] *= cc; O[i][1] *= cc; O[i][2] *= cc; O[i][3] *= cc;
            *(float4*)&Ps[(ty * 4 + i) * 68 + tx * 4] = make_float4(p0, p1, p2, p3);
        }
        __syncthreads();

#pragma unroll 8
        for (int kk = 0; kk < 64; kk++) {
            float4 vv = *(const float4*)&Vs[kk * 64 + tx * 4];
#pragma unroll
            for (int i = 0; i < 4; i++) {
                float pp = Ps[(ty * 4 + i) * 68 + kk];
                O[i][0] = fmaf(pp, vv.x, O[i][0]);
                O[i][1] = fmaf(pp, vv.y, O[i][1]);
                O[i][2] = fmaf(pp, vv.z, O[i][2]);
                O[i][3] = fmaf(pp, vv.w, O[i][3]);
            }
        }
        __syncthreads();
    }

#pragma unroll
    for (int i = 0; i < 4; i++) {
        float invl = 1.0f / lr[i];
        float4 o4 = make_float4(O[i][0] * invl, O[i][1] * invl,
                                O[i][2] * invl, O[i][3] * invl);
        *(float4*)(ctx + (size_t)(q0 + ty * 4 + i) * Hh + hd * DHd + tx * 4) = o4;
    }
}

// ---------------- residual + layernorm ---------------------------------------
__global__ void ln_kernel(const float* __restrict__ a, const float* __restrict__ b,
                          const float* __restrict__ g, const float* __restrict__ be,
                          float* __restrict__ out)
{
    __shared__ float red[8];
    int n = blockIdx.x, c = threadIdx.x;
    int lane = c & 31, w = c >> 5;
    float vv = a[(size_t)n * Hh + c] + b[(size_t)n * Hh + c];
    float s = vv;
#pragma unroll
    for (int off = 16; off; off >>= 1) s += __shfl_xor_sync(0xffffffffu, s, off);
    if (lane == 0) red[w] = s;
    __syncthreads();
    float mu = 0.0f;
#pragma unroll
    for (int i = 0; i < 8; i++) mu += red[i];
    mu *= (1.0f / Hh);
    __syncthreads();
    float dv = vv - mu;
    float sq = dv * dv;
#pragma unroll
    for (int off = 16; off; off >>= 1) sq += __shfl_xor_sync(0xffffffffu, sq, off);
    if (lane == 0) red[w] = sq;
    __syncthreads();
    float var = 0.0f;
#pragma unroll
    for (int i = 0; i < 8; i++) var += red[i];
    var *= (1.0f / Hh);
    float rstd = rsqrtf(var + 1e-5f);
    out[(size_t)n * Hh + c] = dv * rstd * g[c] + be[c];
}

// ---------------- launch ------------------------------------------------------
extern "C" void kernel_launch(void* const* d_in, const int* in_sizes, int n_in,
                              void* d_out, int out_size)
{
    const float* h     = (const float*)d_in[0];
    const int*   ei    = (const int*)d_in[1];
    const float* W_src = (const float*)d_in[2];
    const float* b_src = (const float*)d_in[3];
    const float* W_tgt = (const float*)d_in[4];
    const float* b_tgt = (const float*)d_in[5];
    const float* Wq = (const float*)d_in[6];  const float* bq = (const float*)d_in[7];
    const float* Wk = (const float*)d_in[8];  const float* bk = (const float*)d_in[9];
    const float* Wv = (const float*)d_in[10]; const float* bv = (const float*)d_in[11];
    const float* Wo = (const float*)d_in[12]; const float* bo = (const float*)d_in[13];
    const float* W1 = (const float*)d_in[14]; const float* b1 = (const float*)d_in[15];
    const float* W2 = (const float*)d_in[16]; const float* b2 = (const float*)d_in[17];
    const float* g1 = (const float*)d_in[18]; const float* be1 = (const float*)d_in[19];
    const float* g2 = (const float*)d_in[20]; const float* be2 = (const float*)d_in[21];
    float* out = (float*)d_out;

    float *pX1, *pX2, *pagg, *pq, *pk, *pv, *pctx, *po, *px, *pt, *py, *pbsum, *prw;
    cudaGetSymbolAddress((void**)&pX1,  g_X1);
    cudaGetSymbolAddress((void**)&pX2,  g_X2);
    cudaGetSymbolAddress((void**)&pagg, g_agg);
    cudaGetSymbolAddress((void**)&pq,   g_q);
    cudaGetSymbolAddress((void**)&pk,   g_k);
    cudaGetSymbolAddress((void**)&pv,   g_v);
    cudaGetSymbolAddress((void**)&pctx, g_ctx);
    cudaGetSymbolAddress((void**)&po,   g_o);
    cudaGetSymbolAddress((void**)&px,   g_x);
    cudaGetSymbolAddress((void**)&pt,   g_t);
    cudaGetSymbolAddress((void**)&py,   g_y);
    cudaGetSymbolAddress((void**)&pbsum, g_bsum);
    cudaGetSymbolAddress((void**)&prw,  g_rw);

    // graph preprocessing: deg -> rowptr -> CSR -> segment mean inputs
    zero_kernel<<<Nn / 256, 256>>>();
    deg_kernel<<<Ee / 256, 256>>>(ei);
    prefix_kernel<<<1, 1024>>>();
    fill_kernel<<<Ee / 256, 256>>>(ei);
    aggsum_kernel<<<Nn, 256>>>(h);
    bsum_kernel<<<1, Hh>>>(b_src, b_tgt);

    dim3 gH(Hh / 64, Nn / 64);
    // agg = X1@W_src + X2@W_tgt + rw*(b_src+b_tgt)
    gemm_kernel<0><<<gH, 256>>>(pX1, W_src, nullptr, nullptr, pagg, Nn, Hh, Hh, 0);
    gemm_kernel<0><<<gH, 256>>>(pX2, W_tgt, pbsum, prw, pagg, Nn, Hh, Hh, 1);

    // q/k/v projections
    gemm_kernel<0><<<gH, 256>>>(h,    Wq, bq, nullptr, pq, Nn, Hh, Hh, 0);
    gemm_kernel<0><<<gH, 256>>>(pagg, Wk, bk, nullptr, pk, Nn, Hh, Hh, 0);
    gemm_kernel<0><<<gH, 256>>>(pagg, Wv, bv, nullptr, pv, Nn, Hh, Hh, 0);

    // flash attention
    int smbytes = (3 * 64 * 68 + 64 * 64) * 4;  // 68608 B
    cudaFuncSetAttribute(attn_kernel, cudaFuncAttributeMaxDynamicSharedMemorySize, smbytes);
    attn_kernel<<<dim3(Nn / 64, NHEADS), 256, smbytes>>>(pq, pk, pv, pctx);

    // output projection + residual LN
    gemm_kernel<0><<<gH, 256>>>(pctx, Wo, bo, nullptr, po, Nn, Hh, Hh, 0);
    ln_kernel<<<Nn, 256>>>(h, po, g1, be1, px);

    // FFN (gelu) + residual LN -> output
    gemm_kernel<1><<<dim3(2 * Hh / 64, Nn / 64), 256>>>(px, W1, b1, nullptr, pt, Nn, Hh, 2 * Hh, 0);
    gemm_kernel<0><<<gH, 256>>>(pt, W2, b2, nullptr, py, Nn, 2 * Hh, Hh, 0);
    ln_kernel<<<Nn, 256>>>(px, py, g2, be2, out);

    (void)in_sizes; (void)n_in; (void)out_size;
}